// round 5
// baseline (speedup 1.0000x reference)
#include <cuda_runtime.h>

#define MSGD 128
#define KNB 32
#define NB 8            // nodes per CTA per group (1 per warp)
#define THREADS 256
#define CTAS 296        // 2 CTAs per SM

typedef unsigned long long ull;

// Precomputed operators (allocation-free __device__ scratch)
// g_A4[((e>>2)*128 + d)*4 + (e&3)] = A[d][e],  A = Wk^T Wq  (Qeff = A q + u)
// g_W4[((e>>2)*128 + m)*4 + (e&3)] = Wv[m][e]               (out  = Wv y + bv)
__device__ __align__(16) float g_A4[MSGD * MSGD];
__device__ __align__(16) float g_W4[MSGD * MSGD];
__device__ __align__(16) float g_u[MSGD];   // u = Wk^T bq

// ---------------------------------------------------------------------------
// packed fp32x2 helpers
// ---------------------------------------------------------------------------
__device__ __forceinline__ ull pack2(float x, float y) {
    ull r; asm("mov.b64 %0,{%1,%2};" : "=l"(r) : "f"(x), "f"(y)); return r;
}
__device__ __forceinline__ void fma2(ull& d, ull a, ull b) {
    asm("fma.rn.f32x2 %0,%1,%2,%0;" : "+l"(d) : "l"(a), "l"(b));
}
__device__ __forceinline__ ull mul2(ull a, ull b) {
    ull r; asm("mul.rn.f32x2 %0,%1,%2;" : "=l"(r) : "l"(a), "l"(b)); return r;
}
__device__ __forceinline__ float sum2(ull v) {
    float x, y; asm("mov.b64 {%0,%1},%2;" : "=f"(x), "=f"(y) : "l"(v)); return x + y;
}

// ---------------------------------------------------------------------------
// Prep: A = Wk^T Wq, u = Wk^T bq, Wv repacked; e-pair-friendly float4 layout
// ---------------------------------------------------------------------------
__global__ void prep_kernel(const float* __restrict__ Wq, const float* __restrict__ bq,
                            const float* __restrict__ Wk, const float* __restrict__ Wv) {
    const int e = blockIdx.x;
    const int d = threadIdx.x;
    float acc = 0.f;
#pragma unroll 8
    for (int a = 0; a < MSGD; ++a)
        acc = fmaf(Wk[a * MSGD + d], Wq[a * MSGD + e], acc);
    g_A4[((e >> 2) * MSGD + d) * 4 + (e & 3)] = acc;
    g_W4[((e >> 2) * MSGD + d) * 4 + (e & 3)] = Wv[d * MSGD + e];
    if (e == 0) {
        float u = 0.f;
#pragma unroll 8
        for (int a = 0; a < MSGD; ++a)
            u = fmaf(Wk[a * MSGD + d], bq[a], u);
        g_u[d] = u;
    }
}

// ---------------------------------------------------------------------------
// Main kernel: warp-per-node online-softmax attention, batched GEMM phases.
// smem tiny (sQe + sY); x streamed once via L2-only loads; operators hot in L1.
// ---------------------------------------------------------------------------
__global__ __launch_bounds__(THREADS, 2)
void gac_kernel(const float* __restrict__ qmsg, const float* __restrict__ nmsg,
                const float* __restrict__ bv, float* __restrict__ outp,
                int N, int G) {
    __shared__ __align__(16) float sQe[NB * MSGD];
    __shared__ __align__(16) float sY[NB * MSGD];

    const int t = threadIdx.x;
    const int w = t >> 5;
    const int l = t & 31;
    const int qbase = (w >> 2) * 4;        // node quad for GEMM phases (0 or 4)
    const int dcol  = (w & 3) * 32 + l;    // output column, coalesced per warp

    const ulonglong2* gA = reinterpret_cast<const ulonglong2*>(g_A4);
    const ulonglong2* gW = reinterpret_cast<const ulonglong2*>(g_W4);
    const float uu = g_u[dcol];
    const float bb = bv[dcol];
    const int ctaBase = blockIdx.x * (NB * G);

    // ---- phase A: Qeff[i][dcol] = sum_e A[dcol][e] q_i[e] + u  (4 nodes) ----
    auto phaseA = [&](int nb) {
        int n0 = nb + qbase + 0; if (n0 >= N) n0 = N - 1;
        int n1 = nb + qbase + 1; if (n1 >= N) n1 = N - 1;
        int n2 = nb + qbase + 2; if (n2 >= N) n2 = N - 1;
        int n3 = nb + qbase + 3; if (n3 >= N) n3 = N - 1;
        const ulonglong2* q0 = reinterpret_cast<const ulonglong2*>(qmsg + (size_t)n0 * MSGD);
        const ulonglong2* q1 = reinterpret_cast<const ulonglong2*>(qmsg + (size_t)n1 * MSGD);
        const ulonglong2* q2 = reinterpret_cast<const ulonglong2*>(qmsg + (size_t)n2 * MSGD);
        const ulonglong2* q3 = reinterpret_cast<const ulonglong2*>(qmsg + (size_t)n3 * MSGD);
        ull a0 = 0, a1 = 0, a2 = 0, a3 = 0;
#pragma unroll 8
        for (int e4 = 0; e4 < 32; ++e4) {
            ulonglong2 av = gA[e4 * MSGD + dcol];   // coalesced, L1-resident
            ulonglong2 p0 = q0[e4];                  // broadcast
            ulonglong2 p1 = q1[e4];
            ulonglong2 p2 = q2[e4];
            ulonglong2 p3 = q3[e4];
            fma2(a0, av.x, p0.x); fma2(a0, av.y, p0.y);
            fma2(a1, av.x, p1.x); fma2(a1, av.y, p1.y);
            fma2(a2, av.x, p2.x); fma2(a2, av.y, p2.y);
            fma2(a3, av.x, p3.x); fma2(a3, av.y, p3.y);
        }
        sQe[(qbase + 0) * MSGD + dcol] = sum2(a0) + uu;
        sQe[(qbase + 1) * MSGD + dcol] = sum2(a1) + uu;
        sQe[(qbase + 2) * MSGD + dcol] = sum2(a2) + uu;
        sQe[(qbase + 3) * MSGD + dcol] = sum2(a3) + uu;
    };

    // ---- phase C: out[i][dcol] = sum_e Wv[dcol][e] y_i[e] + bv  (4 nodes) ----
    auto phaseC = [&](int nb) {
        const ulonglong2* y0 = reinterpret_cast<const ulonglong2*>(sY + (qbase + 0) * MSGD);
        const ulonglong2* y1 = reinterpret_cast<const ulonglong2*>(sY + (qbase + 1) * MSGD);
        const ulonglong2* y2 = reinterpret_cast<const ulonglong2*>(sY + (qbase + 2) * MSGD);
        const ulonglong2* y3 = reinterpret_cast<const ulonglong2*>(sY + (qbase + 3) * MSGD);
        ull a0 = 0, a1 = 0, a2 = 0, a3 = 0;
#pragma unroll 8
        for (int e4 = 0; e4 < 32; ++e4) {
            ulonglong2 av = gW[e4 * MSGD + dcol];   // L1-resident
            ulonglong2 p0 = y0[e4];                  // smem broadcast
            ulonglong2 p1 = y1[e4];
            ulonglong2 p2 = y2[e4];
            ulonglong2 p3 = y3[e4];
            fma2(a0, av.x, p0.x); fma2(a0, av.y, p0.y);
            fma2(a1, av.x, p1.x); fma2(a1, av.y, p1.y);
            fma2(a2, av.x, p2.x); fma2(a2, av.y, p2.y);
            fma2(a3, av.x, p3.x); fma2(a3, av.y, p3.y);
        }
        const int n0 = nb + qbase;
        if (n0 + 0 < N) outp[(size_t)(n0 + 0) * MSGD + dcol] = sum2(a0) + bb;
        if (n0 + 1 < N) outp[(size_t)(n0 + 1) * MSGD + dcol] = sum2(a1) + bb;
        if (n0 + 2 < N) outp[(size_t)(n0 + 2) * MSGD + dcol] = sum2(a2) + bb;
        if (n0 + 3 < N) outp[(size_t)(n0 + 3) * MSGD + dcol] = sum2(a3) + bb;
    };

    phaseA(ctaBase);

    for (int g = 0; g < G; ++g) {
        const int nodeBase = ctaBase + g * NB;

        __syncthreads();   // sQe(g) ready

        // ---- attention for node (nodeBase + w): online softmax, x read once ----
        {
            int node = nodeBase + w; if (node >= N) node = N - 1;
            // lane's Qeff slice (d = 4l..4l+3)
            ulonglong2 qv = *reinterpret_cast<const ulonglong2*>(sQe + w * MSGD + 4 * l);
            const float4* xrow = reinterpret_cast<const float4*>(
                nmsg + (size_t)node * (KNB * MSGD)) + l;

            float m = -1e30f, ssum = 0.f;
            ull ya = 0, yb = 0;

#pragma unroll
            for (int kb = 0; kb < KNB; kb += 4) {
                // 4 independent dot-chains for ILP
                float4 v0 = __ldcg(xrow + (kb + 0) * 32);
                float4 v1 = __ldcg(xrow + (kb + 1) * 32);
                float4 v2 = __ldcg(xrow + (kb + 2) * 32);
                float4 v3 = __ldcg(xrow + (kb + 3) * 32);
                ull x0a = pack2(v0.x, v0.y), x0b = pack2(v0.z, v0.w);
                ull x1a = pack2(v1.x, v1.y), x1b = pack2(v1.z, v1.w);
                ull x2a = pack2(v2.x, v2.y), x2b = pack2(v2.z, v2.w);
                ull x3a = pack2(v3.x, v3.y), x3b = pack2(v3.z, v3.w);
                ull d0 = 0, d1 = 0, d2 = 0, d3 = 0;
                fma2(d0, x0a, qv.x); fma2(d0, x0b, qv.y);
                fma2(d1, x1a, qv.x); fma2(d1, x1b, qv.y);
                fma2(d2, x2a, qv.x); fma2(d2, x2b, qv.y);
                fma2(d3, x3a, qv.x); fma2(d3, x3b, qv.y);
                float s0 = sum2(d0), s1 = sum2(d1), s2 = sum2(d2), s3 = sum2(d3);
#pragma unroll
                for (int o = 16; o > 0; o >>= 1) {
                    s0 += __shfl_xor_sync(0xffffffffu, s0, o);
                    s1 += __shfl_xor_sync(0xffffffffu, s1, o);
                    s2 += __shfl_xor_sync(0xffffffffu, s2, o);
                    s3 += __shfl_xor_sync(0xffffffffu, s3, o);
                }
                const float sc = 0.08838834764831843f;  // 1/sqrt(128)
                s0 *= sc; s1 *= sc; s2 *= sc; s3 *= sc;
                float mn = fmaxf(fmaxf(fmaxf(fmaxf(m, s0), s1), s2), s3);
                float r  = __expf(m - mn);
                float p0 = __expf(s0 - mn), p1 = __expf(s1 - mn);
                float p2 = __expf(s2 - mn), p3 = __expf(s3 - mn);
                ssum = ssum * r + p0 + p1 + p2 + p3;
                ull rr = pack2(r, r);
                ull pp0 = pack2(p0, p0), pp1 = pack2(p1, p1);
                ull pp2 = pack2(p2, p2), pp3 = pack2(p3, p3);
                ya = mul2(ya, rr);
                fma2(ya, pp0, x0a); fma2(ya, pp1, x1a);
                fma2(ya, pp2, x2a); fma2(ya, pp3, x3a);
                yb = mul2(yb, rr);
                fma2(yb, pp0, x0b); fma2(yb, pp1, x1b);
                fma2(yb, pp2, x2b); fma2(yb, pp3, x3b);
                m = mn;
            }
            const float inv = 1.0f / ssum;
            ull iv = pack2(inv, inv);
            ulonglong2 yy; yy.x = mul2(ya, iv); yy.y = mul2(yb, iv);
            *reinterpret_cast<ulonglong2*>(sY + w * MSGD + 4 * l) = yy;
        }

        __syncthreads();   // sY(g) ready; sQe free

        if (g + 1 < G) phaseA(nodeBase + NB);   // next group's Qeff
        phaseC(nodeBase);                        // output for this group
    }
}

// ---------------------------------------------------------------------------
// Harness entry
// ---------------------------------------------------------------------------
extern "C" void kernel_launch(void* const* d_in, const int* in_sizes, int n_in,
                              void* d_out, int out_size) {
    const float* qmsg = (const float*)d_in[0];  // [N,128]
    const float* nmsg = (const float*)d_in[1];  // [N,32,128]
    const float* Wq   = (const float*)d_in[2];  // [128,128]
    const float* bq   = (const float*)d_in[3];  // [128]
    const float* Wk   = (const float*)d_in[4];  // [128,128]
    // d_in[5] = bk: softmax-invariant constant, mathematically irrelevant
    const float* Wv   = (const float*)d_in[6];  // [128,128]
    const float* bv   = (const float*)d_in[7];  // [128]
    float* out = (float*)d_out;

    const int N = in_sizes[0] / MSGD;

    prep_kernel<<<MSGD, MSGD>>>(Wq, bq, Wk, Wv);

    // one-wave grid at 2 CTAs/SM: 296 CTAs, G groups of 8 nodes each
    int G = (N + NB * CTAS - 1) / (NB * CTAS);
    if (G < 1) G = 1;
    int grid = (N + NB * G - 1) / (NB * G);

    gac_kernel<<<grid, THREADS>>>(qmsg, nmsg, bv, out, N, G);
}

// round 6
// speedup vs baseline: 1.4291x; 1.4291x over previous
#include <cuda_runtime.h>

#define MSGD 128
#define KNB 32
#define NB 8            // nodes per CTA per group (1 per warp)
#define THREADS 256
#define CTAS 296        // 2 CTAs per SM target

typedef unsigned long long ull;

// Precomputed operators (allocation-free __device__ scratch)
// g_A4[((e>>2)*128 + d)*4 + (e&3)] = A[d][e],  A = Wk^T Wq  (Qeff = A q + u)
// g_W4[((e>>2)*128 + m)*4 + (e&3)] = Wv[m][e]               (out  = Wv y + bv)
__device__ __align__(16) float g_A4[MSGD * MSGD];
__device__ __align__(16) float g_W4[MSGD * MSGD];
__device__ __align__(16) float g_u[MSGD];   // u = Wk^T bq

// ---------------------------------------------------------------------------
// packed fp32x2 helpers
// ---------------------------------------------------------------------------
__device__ __forceinline__ ull pack2(float x, float y) {
    ull r; asm("mov.b64 %0,{%1,%2};" : "=l"(r) : "f"(x), "f"(y)); return r;
}
__device__ __forceinline__ void fma2(ull& d, ull a, ull b) {
    asm("fma.rn.f32x2 %0,%1,%2,%0;" : "+l"(d) : "l"(a), "l"(b));
}
__device__ __forceinline__ ull mul2(ull a, ull b) {
    ull r; asm("mul.rn.f32x2 %0,%1,%2;" : "=l"(r) : "l"(a), "l"(b)); return r;
}
__device__ __forceinline__ float sum2(ull v) {
    float x, y; asm("mov.b64 {%0,%1},%2;" : "=f"(x), "=f"(y) : "l"(v)); return x + y;
}

// ---------------------------------------------------------------------------
// Prep: A = Wk^T Wq, u = Wk^T bq, Wv repacked; e-pair-friendly float4 layout
// ---------------------------------------------------------------------------
__global__ void prep_kernel(const float* __restrict__ Wq, const float* __restrict__ bq,
                            const float* __restrict__ Wk, const float* __restrict__ Wv) {
    const int e = blockIdx.x;
    const int d = threadIdx.x;
    float acc = 0.f;
#pragma unroll 8
    for (int a = 0; a < MSGD; ++a)
        acc = fmaf(Wk[a * MSGD + d], Wq[a * MSGD + e], acc);
    g_A4[((e >> 2) * MSGD + d) * 4 + (e & 3)] = acc;
    g_W4[((e >> 2) * MSGD + d) * 4 + (e & 3)] = Wv[d * MSGD + e];
    if (e == 0) {
        float u = 0.f;
#pragma unroll 8
        for (int a = 0; a < MSGD; ++a)
            u = fmaf(Wk[a * MSGD + d], bq[a], u);
        g_u[d] = u;
    }
}

// ---------------------------------------------------------------------------
// Main kernel: warp-per-node attention (reduce-scatter scores, online softmax,
// register-resident y), batched GEMM phases. x streamed once via L2-only loads.
// ---------------------------------------------------------------------------
__global__ __launch_bounds__(THREADS, 2)
void gac_kernel(const float* __restrict__ qmsg, const float* __restrict__ nmsg,
                const float* __restrict__ bv, float* __restrict__ outp,
                int N, int G) {
    __shared__ __align__(16) float sQe[NB * MSGD];
    __shared__ __align__(16) float sY[NB * MSGD];

    const int t = threadIdx.x;
    const int w = t >> 5;
    const int l = t & 31;
    const int qbase = (w >> 2) * 4;        // node quad for GEMM phases (0 or 4)
    const int dcol  = (w & 3) * 32 + l;    // output column, coalesced per warp

    const ulonglong2* gA = reinterpret_cast<const ulonglong2*>(g_A4);
    const ulonglong2* gW = reinterpret_cast<const ulonglong2*>(g_W4);
    const float uu = g_u[dcol];
    const float bb = bv[dcol];
    const int ctaBase = blockIdx.x * (NB * G);

    // ---- phase A: Qeff[i][dcol] = sum_e A[dcol][e] q_i[e] + u  (4 nodes) ----
    auto phaseA = [&](int nb) {
        int n0 = nb + qbase + 0; if (n0 >= N) n0 = N - 1;
        int n1 = nb + qbase + 1; if (n1 >= N) n1 = N - 1;
        int n2 = nb + qbase + 2; if (n2 >= N) n2 = N - 1;
        int n3 = nb + qbase + 3; if (n3 >= N) n3 = N - 1;
        const ulonglong2* q0 = reinterpret_cast<const ulonglong2*>(qmsg + (size_t)n0 * MSGD);
        const ulonglong2* q1 = reinterpret_cast<const ulonglong2*>(qmsg + (size_t)n1 * MSGD);
        const ulonglong2* q2 = reinterpret_cast<const ulonglong2*>(qmsg + (size_t)n2 * MSGD);
        const ulonglong2* q3 = reinterpret_cast<const ulonglong2*>(qmsg + (size_t)n3 * MSGD);
        ull a0 = 0, a1 = 0, a2 = 0, a3 = 0;
#pragma unroll 8
        for (int e4 = 0; e4 < 32; ++e4) {
            ulonglong2 av = gA[e4 * MSGD + dcol];   // coalesced, L1-resident
            ulonglong2 p0 = q0[e4];                  // broadcast
            ulonglong2 p1 = q1[e4];
            ulonglong2 p2 = q2[e4];
            ulonglong2 p3 = q3[e4];
            fma2(a0, av.x, p0.x); fma2(a0, av.y, p0.y);
            fma2(a1, av.x, p1.x); fma2(a1, av.y, p1.y);
            fma2(a2, av.x, p2.x); fma2(a2, av.y, p2.y);
            fma2(a3, av.x, p3.x); fma2(a3, av.y, p3.y);
        }
        sQe[(qbase + 0) * MSGD + dcol] = sum2(a0) + uu;
        sQe[(qbase + 1) * MSGD + dcol] = sum2(a1) + uu;
        sQe[(qbase + 2) * MSGD + dcol] = sum2(a2) + uu;
        sQe[(qbase + 3) * MSGD + dcol] = sum2(a3) + uu;
    };

    // ---- phase C: out[i][dcol] = sum_e Wv[dcol][e] y_i[e] + bv  (4 nodes) ----
    auto phaseC = [&](int nb) {
        const ulonglong2* y0 = reinterpret_cast<const ulonglong2*>(sY + (qbase + 0) * MSGD);
        const ulonglong2* y1 = reinterpret_cast<const ulonglong2*>(sY + (qbase + 1) * MSGD);
        const ulonglong2* y2 = reinterpret_cast<const ulonglong2*>(sY + (qbase + 2) * MSGD);
        const ulonglong2* y3 = reinterpret_cast<const ulonglong2*>(sY + (qbase + 3) * MSGD);
        ull a0 = 0, a1 = 0, a2 = 0, a3 = 0;
#pragma unroll 8
        for (int e4 = 0; e4 < 32; ++e4) {
            ulonglong2 av = gW[e4 * MSGD + dcol];   // L1-resident
            ulonglong2 p0 = y0[e4];                  // smem broadcast
            ulonglong2 p1 = y1[e4];
            ulonglong2 p2 = y2[e4];
            ulonglong2 p3 = y3[e4];
            fma2(a0, av.x, p0.x); fma2(a0, av.y, p0.y);
            fma2(a1, av.x, p1.x); fma2(a1, av.y, p1.y);
            fma2(a2, av.x, p2.x); fma2(a2, av.y, p2.y);
            fma2(a3, av.x, p3.x); fma2(a3, av.y, p3.y);
        }
        const int n0 = nb + qbase;
        if (n0 + 0 < N) outp[(size_t)(n0 + 0) * MSGD + dcol] = sum2(a0) + bb;
        if (n0 + 1 < N) outp[(size_t)(n0 + 1) * MSGD + dcol] = sum2(a1) + bb;
        if (n0 + 2 < N) outp[(size_t)(n0 + 2) * MSGD + dcol] = sum2(a2) + bb;
        if (n0 + 3 < N) outp[(size_t)(n0 + 3) * MSGD + dcol] = sum2(a3) + bb;
    };

    phaseA(ctaBase);

    for (int g = 0; g < G; ++g) {
        const int nodeBase = ctaBase + g * NB;

        __syncthreads();   // sQe(g) ready

        // ---- attention for node (nodeBase + w) ----
        {
            int node = nodeBase + w; if (node >= N) node = N - 1;
            // lane's Qeff slice (d = 4l..4l+3) as two packed pairs
            ulonglong2 qv = *reinterpret_cast<const ulonglong2*>(sQe + w * MSGD + 4 * l);
            const ulonglong2* xp = reinterpret_cast<const ulonglong2*>(
                nmsg + (size_t)node * (KNB * MSGD)) + l;

            float m = -1e30f, ssum = 0.f;
            ull ya = 0, yb = 0;
            const bool h16 = (l & 16), h8 = (l & 8), h4 = (l & 4);

#pragma unroll
            for (int b = 0; b < 4; ++b) {
                // load 8 neighbors' 16B slices (coalesced, L2-only)
                ulonglong2 x0 = __ldcg(xp + (b * 8 + 0) * 32);
                ulonglong2 x1 = __ldcg(xp + (b * 8 + 1) * 32);
                ulonglong2 x2 = __ldcg(xp + (b * 8 + 2) * 32);
                ulonglong2 x3 = __ldcg(xp + (b * 8 + 3) * 32);
                ulonglong2 x4 = __ldcg(xp + (b * 8 + 4) * 32);
                ulonglong2 x5 = __ldcg(xp + (b * 8 + 5) * 32);
                ulonglong2 x6 = __ldcg(xp + (b * 8 + 6) * 32);
                ulonglong2 x7 = __ldcg(xp + (b * 8 + 7) * 32);

                // per-lane 4-dim partial dot for each neighbor
                ull d0 = 0, d1 = 0, d2 = 0, d3 = 0, d4 = 0, d5 = 0, d6 = 0, d7 = 0;
                fma2(d0, x0.x, qv.x); fma2(d0, x0.y, qv.y);
                fma2(d1, x1.x, qv.x); fma2(d1, x1.y, qv.y);
                fma2(d2, x2.x, qv.x); fma2(d2, x2.y, qv.y);
                fma2(d3, x3.x, qv.x); fma2(d3, x3.y, qv.y);
                fma2(d4, x4.x, qv.x); fma2(d4, x4.y, qv.y);
                fma2(d5, x5.x, qv.x); fma2(d5, x5.y, qv.y);
                fma2(d6, x6.x, qv.x); fma2(d6, x6.y, qv.y);
                fma2(d7, x7.x, qv.x); fma2(d7, x7.y, qv.y);
                float p0 = sum2(d0), p1 = sum2(d1), p2 = sum2(d2), p3 = sum2(d3);
                float p4 = sum2(d4), p5 = sum2(d5), p6 = sum2(d6), p7 = sum2(d7);

                // reduce-scatter: 9 shfls total -> score of neighbor (b*8 + (l>>2)&7)
                float v, o, k, q0r, q1r, q2r, q3r, r0, r1, s;
                v = h16 ? p0 : p4; o = __shfl_xor_sync(~0u, v, 16); k = h16 ? p4 : p0; q0r = k + o;
                v = h16 ? p1 : p5; o = __shfl_xor_sync(~0u, v, 16); k = h16 ? p5 : p1; q1r = k + o;
                v = h16 ? p2 : p6; o = __shfl_xor_sync(~0u, v, 16); k = h16 ? p6 : p2; q2r = k + o;
                v = h16 ? p3 : p7; o = __shfl_xor_sync(~0u, v, 16); k = h16 ? p7 : p3; q3r = k + o;
                v = h8 ? q0r : q2r; o = __shfl_xor_sync(~0u, v, 8); k = h8 ? q2r : q0r; r0 = k + o;
                v = h8 ? q1r : q3r; o = __shfl_xor_sync(~0u, v, 8); k = h8 ? q3r : q1r; r1 = k + o;
                v = h4 ? r0 : r1;   o = __shfl_xor_sync(~0u, v, 4); k = h4 ? r1 : r0;   s = k + o;
                s += __shfl_xor_sync(~0u, s, 2);
                s += __shfl_xor_sync(~0u, s, 1);
                s *= 0.08838834764831843f;   // 1/sqrt(128)

                // block max over the 8 quads
                float mb = s;
                mb = fmaxf(mb, __shfl_xor_sync(~0u, mb, 4));
                mb = fmaxf(mb, __shfl_xor_sync(~0u, mb, 8));
                mb = fmaxf(mb, __shfl_xor_sync(~0u, mb, 16));
                float mn = fmaxf(m, mb);
                float rs = __expf(m - mn);
                float pe = __expf(s - mn);     // this quad's neighbor weight
                float ps = pe;
                ps += __shfl_xor_sync(~0u, ps, 4);
                ps += __shfl_xor_sync(~0u, ps, 8);
                ps += __shfl_xor_sync(~0u, ps, 16);
                ssum = ssum * rs + ps;
                m = mn;

                // y rescale + accumulate
                ull rr = pack2(rs, rs);
                ya = mul2(ya, rr); yb = mul2(yb, rr);
                float pj;
                ull pp;
                pj = __shfl_sync(~0u, pe, 0);  pp = pack2(pj, pj); fma2(ya, pp, x0.x); fma2(yb, pp, x0.y);
                pj = __shfl_sync(~0u, pe, 4);  pp = pack2(pj, pj); fma2(ya, pp, x1.x); fma2(yb, pp, x1.y);
                pj = __shfl_sync(~0u, pe, 8);  pp = pack2(pj, pj); fma2(ya, pp, x2.x); fma2(yb, pp, x2.y);
                pj = __shfl_sync(~0u, pe, 12); pp = pack2(pj, pj); fma2(ya, pp, x3.x); fma2(yb, pp, x3.y);
                pj = __shfl_sync(~0u, pe, 16); pp = pack2(pj, pj); fma2(ya, pp, x4.x); fma2(yb, pp, x4.y);
                pj = __shfl_sync(~0u, pe, 20); pp = pack2(pj, pj); fma2(ya, pp, x5.x); fma2(yb, pp, x5.y);
                pj = __shfl_sync(~0u, pe, 24); pp = pack2(pj, pj); fma2(ya, pp, x6.x); fma2(yb, pp, x6.y);
                pj = __shfl_sync(~0u, pe, 28); pp = pack2(pj, pj); fma2(ya, pp, x7.x); fma2(yb, pp, x7.y);
            }
            const float inv = 1.0f / ssum;
            ull iv = pack2(inv, inv);
            ulonglong2 yy; yy.x = mul2(ya, iv); yy.y = mul2(yb, iv);
            *reinterpret_cast<ulonglong2*>(sY + w * MSGD + 4 * l) = yy;
        }

        __syncthreads();   // sY(g) ready; sQe free

        if (g + 1 < G) phaseA(nodeBase + NB);   // next group's Qeff
        phaseC(nodeBase);                        // output for this group
    }
}

// ---------------------------------------------------------------------------
// Harness entry
// ---------------------------------------------------------------------------
extern "C" void kernel_launch(void* const* d_in, const int* in_sizes, int n_in,
                              void* d_out, int out_size) {
    const float* qmsg = (const float*)d_in[0];  // [N,128]
    const float* nmsg = (const float*)d_in[1];  // [N,32,128]
    const float* Wq   = (const float*)d_in[2];  // [128,128]
    const float* bq   = (const float*)d_in[3];  // [128]
    const float* Wk   = (const float*)d_in[4];  // [128,128]
    // d_in[5] = bk: softmax-invariant constant, mathematically irrelevant
    const float* Wv   = (const float*)d_in[6];  // [128,128]
    const float* bv   = (const float*)d_in[7];  // [128]
    float* out = (float*)d_out;

    const int N = in_sizes[0] / MSGD;

    prep_kernel<<<MSGD, MSGD>>>(Wq, bq, Wk, Wv);

    // one-wave grid at 2 CTAs/SM: G groups of 8 nodes each
    int G = (N + NB * CTAS - 1) / (NB * CTAS);
    if (G < 1) G = 1;
    int grid = (N + NB * G - 1) / (NB * G);

    gac_kernel<<<grid, THREADS>>>(qmsg, nmsg, bv, out, N, G);
}